// round 1
// baseline (speedup 1.0000x reference)
#include <cuda_runtime.h>

// 3D Haar DWT: x (2,32,64,128,128) fp32 -> 8 subbands each (2,32,32,64,64),
// concatenated in order (LLL,LLH,LHL,LHH,HLL,HLH,HHL,HHH),
// bit2 = high-pass along D, bit1 = high-pass along H, bit0 = high-pass along W.
//
// Per output element [nc, r, p, q] of subband (hd,hh,hw):
//   c^3 * sum_{a,b,e in {0,1}} s_d(a) s_h(b) s_w(e) * x[nc, 2r+a, 2p+b, 2q+e]
// with s(1) = -1 for the high-pass axis, else +1, and c = 1/sqrt(2).

constexpr int IN_D = 64, IN_H = 128, IN_W = 128;
constexpr int OD = 32, OP = 64, OQ = 64;
constexpr int NC = 64;                         // N*C = 2*32
constexpr long long SUB = (long long)NC * OD * OP * OQ;  // 8388608 elems per subband

__device__ __forceinline__ float4 f4add(float4 a, float4 b) {
    return make_float4(a.x + b.x, a.y + b.y, a.z + b.z, a.w + b.w);
}
__device__ __forceinline__ float4 f4sub(float4 a, float4 b) {
    return make_float4(a.x - b.x, a.y - b.y, a.z - b.z, a.w - b.w);
}
__device__ __forceinline__ float4 f4scale(float4 a, float s) {
    return make_float4(a.x * s, a.y * s, a.z * s, a.w * s);
}

struct WPair { float4 lo, hi; };

// 8 consecutive w-values (as two float4s) -> 4 low-pass + 4 high-pass (w axis)
__device__ __forceinline__ WPair wsplit(float4 u, float4 v) {
    WPair r;
    r.lo = make_float4(u.x + u.y, u.z + u.w, v.x + v.y, v.z + v.w);
    r.hi = make_float4(u.x - u.y, u.z - u.w, v.x - v.y, v.z - v.w);
    return r;
}

__global__ void __launch_bounds__(256) dwt3d_haar_kernel(
    const float* __restrict__ x, float* __restrict__ out)
{
    int idx = blockIdx.x * 256 + threadIdx.x;
    // decode: q4 (16 per row of 64 q), p (64), r (32), nc (64)
    int q4 = idx & 15;
    int t  = idx >> 4;
    int p  = t & 63;
    t >>= 6;
    int r  = t & 31;
    int nc = t >> 5;

    const float* base = x
        + (((long long)nc * IN_D + 2 * r) * IN_H + 2 * p) * IN_W
        + q4 * 8;

    const float4* p00 = (const float4*)(base);                       // d=0, h=0
    const float4* p01 = (const float4*)(base + IN_W);                // d=0, h=1
    const float4* p10 = (const float4*)(base + IN_H * IN_W);         // d=1, h=0
    const float4* p11 = (const float4*)(base + IN_H * IN_W + IN_W);  // d=1, h=1

    float4 a0 = p00[0], a1 = p00[1];
    float4 b0 = p01[0], b1 = p01[1];
    float4 c0 = p10[0], c1 = p10[1];
    float4 d0 = p11[0], d1 = p11[1];

    // Stage 1: w-axis butterflies per row
    WPair w00 = wsplit(a0, a1);
    WPair w01 = wsplit(b0, b1);
    WPair w10 = wsplit(c0, c1);
    WPair w11 = wsplit(d0, d1);

    // Stage 2: h-axis butterflies per d-slice
    float4 d0_ll = f4add(w00.lo, w01.lo);  // h-low,  w-low
    float4 d0_lh = f4add(w00.hi, w01.hi);  // h-low,  w-high
    float4 d0_hl = f4sub(w00.lo, w01.lo);  // h-high, w-low
    float4 d0_hh = f4sub(w00.hi, w01.hi);  // h-high, w-high
    float4 d1_ll = f4add(w10.lo, w11.lo);
    float4 d1_lh = f4add(w10.hi, w11.hi);
    float4 d1_hl = f4sub(w10.lo, w11.lo);
    float4 d1_hh = f4sub(w10.hi, w11.hi);

    // Stage 3: d-axis butterflies + scale
    const float s = 0.3535533905932738f;  // (1/sqrt(2))^3

    float4 o0 = f4scale(f4add(d0_ll, d1_ll), s);  // LLL
    float4 o1 = f4scale(f4add(d0_lh, d1_lh), s);  // LLH
    float4 o2 = f4scale(f4add(d0_hl, d1_hl), s);  // LHL
    float4 o3 = f4scale(f4add(d0_hh, d1_hh), s);  // LHH
    float4 o4 = f4scale(f4sub(d0_ll, d1_ll), s);  // HLL
    float4 o5 = f4scale(f4sub(d0_lh, d1_lh), s);  // HLH
    float4 o6 = f4scale(f4sub(d0_hl, d1_hl), s);  // HHL
    float4 o7 = f4scale(f4sub(d0_hh, d1_hh), s);  // HHH

    long long o = (((long long)nc * OD + r) * OP + p) * OQ + q4 * 4;
    float4* outp = (float4*)(out + o);
    const long long sub4 = SUB / 4;  // subband stride in float4 units

    outp[0 * sub4] = o0;
    outp[1 * sub4] = o1;
    outp[2 * sub4] = o2;
    outp[3 * sub4] = o3;
    outp[4 * sub4] = o4;
    outp[5 * sub4] = o5;
    outp[6 * sub4] = o6;
    outp[7 * sub4] = o7;
}

extern "C" void kernel_launch(void* const* d_in, const int* in_sizes, int n_in,
                              void* d_out, int out_size) {
    const float* x = (const float*)d_in[0];
    float* out = (float*)d_out;

    // total threads: 64 * 32 * 64 * 16 = 2,097,152
    const int total = NC * OD * OP * (OQ / 4);
    dwt3d_haar_kernel<<<total / 256, 256>>>(x, out);
}

// round 2
// speedup vs baseline: 1.0004x; 1.0004x over previous
#include <cuda_runtime.h>

// 3D Haar DWT: x (2,32,64,128,128) fp32 -> 8 subbands each (2,32,32,64,64),
// concatenated in order (LLL,LLH,LHL,LHH,HLL,HLH,HHL,HHH).
// Pure streaming kernel; R1: streaming cache hints (__ldcs/__stcs) to keep
// the 512MB one-shot traffic from thrashing L2 (evict-first policy).

constexpr int IN_D = 64, IN_H = 128, IN_W = 128;
constexpr int OD = 32, OP = 64, OQ = 64;
constexpr int NC = 64;                         // N*C = 2*32
constexpr long long SUB = (long long)NC * OD * OP * OQ;  // elems per subband

__device__ __forceinline__ float4 f4add(float4 a, float4 b) {
    return make_float4(a.x + b.x, a.y + b.y, a.z + b.z, a.w + b.w);
}
__device__ __forceinline__ float4 f4sub(float4 a, float4 b) {
    return make_float4(a.x - b.x, a.y - b.y, a.z - b.z, a.w - b.w);
}
__device__ __forceinline__ float4 f4scale(float4 a, float s) {
    return make_float4(a.x * s, a.y * s, a.z * s, a.w * s);
}

struct WPair { float4 lo, hi; };

__device__ __forceinline__ WPair wsplit(float4 u, float4 v) {
    WPair r;
    r.lo = make_float4(u.x + u.y, u.z + u.w, v.x + v.y, v.z + v.w);
    r.hi = make_float4(u.x - u.y, u.z - u.w, v.x - v.y, v.z - v.w);
    return r;
}

__global__ void __launch_bounds__(256) dwt3d_haar_kernel(
    const float* __restrict__ x, float* __restrict__ out)
{
    int idx = blockIdx.x * 256 + threadIdx.x;
    int q4 = idx & 15;
    int t  = idx >> 4;
    int p  = t & 63;
    t >>= 6;
    int r  = t & 31;
    int nc = t >> 5;

    const float* base = x
        + (((long long)nc * IN_D + 2 * r) * IN_H + 2 * p) * IN_W
        + q4 * 8;

    const float4* p00 = (const float4*)(base);                       // d=0, h=0
    const float4* p01 = (const float4*)(base + IN_W);                // d=0, h=1
    const float4* p10 = (const float4*)(base + IN_H * IN_W);         // d=1, h=0
    const float4* p11 = (const float4*)(base + IN_H * IN_W + IN_W);  // d=1, h=1

    // Streaming loads (evict-first): data has zero reuse beyond this thread.
    float4 a0 = __ldcs(p00),     a1 = __ldcs(p00 + 1);
    float4 b0 = __ldcs(p01),     b1 = __ldcs(p01 + 1);
    float4 c0 = __ldcs(p10),     c1 = __ldcs(p10 + 1);
    float4 d0 = __ldcs(p11),     d1 = __ldcs(p11 + 1);

    // Stage 1: w-axis butterflies per row
    WPair w00 = wsplit(a0, a1);
    WPair w01 = wsplit(b0, b1);
    WPair w10 = wsplit(c0, c1);
    WPair w11 = wsplit(d0, d1);

    // Stage 2: h-axis butterflies per d-slice
    float4 d0_ll = f4add(w00.lo, w01.lo);
    float4 d0_lh = f4add(w00.hi, w01.hi);
    float4 d0_hl = f4sub(w00.lo, w01.lo);
    float4 d0_hh = f4sub(w00.hi, w01.hi);
    float4 d1_ll = f4add(w10.lo, w11.lo);
    float4 d1_lh = f4add(w10.hi, w11.hi);
    float4 d1_hl = f4sub(w10.lo, w11.lo);
    float4 d1_hh = f4sub(w10.hi, w11.hi);

    // Stage 3: d-axis butterflies + scale
    const float s = 0.3535533905932738f;  // (1/sqrt(2))^3

    float4 o0 = f4scale(f4add(d0_ll, d1_ll), s);
    float4 o1 = f4scale(f4add(d0_lh, d1_lh), s);
    float4 o2 = f4scale(f4add(d0_hl, d1_hl), s);
    float4 o3 = f4scale(f4add(d0_hh, d1_hh), s);
    float4 o4 = f4scale(f4sub(d0_ll, d1_ll), s);
    float4 o5 = f4scale(f4sub(d0_lh, d1_lh), s);
    float4 o6 = f4scale(f4sub(d0_hl, d1_hl), s);
    float4 o7 = f4scale(f4sub(d0_hh, d1_hh), s);

    long long o = (((long long)nc * OD + r) * OP + p) * OQ + q4 * 4;
    float4* outp = (float4*)(out + o);
    const long long sub4 = SUB / 4;

    // Streaming stores (evict-first): no consumer in this kernel.
    __stcs(outp + 0 * sub4, o0);
    __stcs(outp + 1 * sub4, o1);
    __stcs(outp + 2 * sub4, o2);
    __stcs(outp + 3 * sub4, o3);
    __stcs(outp + 4 * sub4, o4);
    __stcs(outp + 5 * sub4, o5);
    __stcs(outp + 6 * sub4, o6);
    __stcs(outp + 7 * sub4, o7);
}

extern "C" void kernel_launch(void* const* d_in, const int* in_sizes, int n_in,
                              void* d_out, int out_size) {
    const float* x = (const float*)d_in[0];
    float* out = (float*)d_out;

    const int total = NC * OD * OP * (OQ / 4);  // 2,097,152 threads
    dwt3d_haar_kernel<<<total / 256, 256>>>(x, out);
}